// round 2
// baseline (speedup 1.0000x reference)
#include <cuda_runtime.h>

// ---------------------------------------------------------------------------
// RILayer: out = r0*x + r1*A1@x + r2*A2@roll(x,1) + r3*A3@roll(x,2)
// Ak: scatter-add SpMM over 640K edges, D=128, N=100000.
// rk = relu(zk)/(sum relu + 1e-6), zk are (1,1) scalars on device.
//
// NOTE: edge_index arrives as int32 (JAX x64 disabled downgrades the
// requested int64), hence const int* below. Reading it as int64 was the
// round-1 illegal-access.
//
// Strategy:
//   1. init kernel: out[i] = r0 * x[i]            (float4)
//   2. 3x edge kernel: warp per edge, lane owns 4 columns.
//      roll handled by (c - SHIFT) & 127 on the gathered column.
//      scatter via red.global.add.v4.f32 (16B vector reduction, sm_90+).
// ---------------------------------------------------------------------------

#define N_NODES 100000
#define D 128
#define N_EDGES 640000

__device__ __forceinline__ void red_add_v4(float* addr, float a, float b, float c, float d) {
    asm volatile("red.global.add.v4.f32 [%0], {%1,%2,%3,%4};"
                 :: "l"(addr), "f"(a), "f"(b), "f"(c), "f"(d)
                 : "memory");
}

__device__ __forceinline__ float order_weight(const float* z0, const float* z1,
                                              const float* z2, const float* z3,
                                              int which) {
    float r0 = fmaxf(*z0, 0.0f);
    float r1 = fmaxf(*z1, 0.0f);
    float r2 = fmaxf(*z2, 0.0f);
    float r3 = fmaxf(*z3, 0.0f);
    float inv = 1.0f / (r0 + r1 + r2 + r3 + 1e-6f);
    float r = (which == 0) ? r0 : (which == 1) ? r1 : (which == 2) ? r2 : r3;
    return r * inv;
}

// out[i] = r0 * x[i], vectorized float4.  n4 = N_NODES * D / 4.
__global__ void init_kernel(const float* __restrict__ x, float* __restrict__ out,
                            const float* __restrict__ z0, const float* __restrict__ z1,
                            const float* __restrict__ z2, const float* __restrict__ z3,
                            int n4) {
    int t = blockIdx.x * blockDim.x + threadIdx.x;
    if (t >= n4) return;
    float s = order_weight(z0, z1, z2, z3, 0);
    float4 v = reinterpret_cast<const float4*>(x)[t];
    v.x *= s; v.y *= s; v.z *= s; v.w *= s;
    reinterpret_cast<float4*>(out)[t] = v;
}

// One warp per edge. Lane l handles out columns [4l, 4l+4).
// Gathered column is (c + j - SHIFT) & 127 to implement jnp.roll(x, SHIFT, axis=1).
template <int SHIFT, int RIDX>
__global__ void edge_kernel(const float* __restrict__ x,
                            const int* __restrict__ ei,   // [2, E] int32: src row, then dst row
                            const float* __restrict__ w,
                            float* __restrict__ out,
                            const float* __restrict__ z0, const float* __restrict__ z1,
                            const float* __restrict__ z2, const float* __restrict__ z3,
                            int E) {
    int gtid = blockIdx.x * blockDim.x + threadIdx.x;
    int e    = gtid >> 5;
    int lane = gtid & 31;
    if (e >= E) return;

    float rk = order_weight(z0, z1, z2, z3, RIDX);

    int src = __ldg(&ei[e]);        // row that accumulates
    int dst = __ldg(&ei[E + e]);    // gathered neighbor
    float wk = __ldg(&w[e]) * rk;

    const float* xr = x + (long long)dst * D;
    int c = lane * 4;

    float a, b, cc, d;
    if (SHIFT == 0) {
        float4 v = reinterpret_cast<const float4*>(xr)[lane];
        a = v.x; b = v.y; cc = v.z; d = v.w;
    } else {
        a  = __ldg(&xr[(c + 0 - SHIFT) & (D - 1)]);
        b  = __ldg(&xr[(c + 1 - SHIFT) & (D - 1)]);
        cc = __ldg(&xr[(c + 2 - SHIFT) & (D - 1)]);
        d  = __ldg(&xr[(c + 3 - SHIFT) & (D - 1)]);
    }

    red_add_v4(out + (long long)src * D + c, a * wk, b * wk, cc * wk, d * wk);
}

extern "C" void kernel_launch(void* const* d_in, const int* in_sizes, int n_in,
                              void* d_out, int out_size) {
    const float* x   = (const float*)d_in[0];
    const int*   ei1 = (const int*)d_in[1];
    const float* w1  = (const float*)d_in[2];
    const int*   ei2 = (const int*)d_in[3];
    const float* w2  = (const float*)d_in[4];
    const int*   ei3 = (const int*)d_in[5];
    const float* w3  = (const float*)d_in[6];
    const float* z0  = (const float*)d_in[7];
    const float* z1  = (const float*)d_in[8];
    const float* z2  = (const float*)d_in[9];
    const float* z3  = (const float*)d_in[10];
    float* out = (float*)d_out;

    const int E = N_EDGES;

    // 1) out = r0 * x
    {
        int n4 = N_NODES * D / 4;
        int threads = 256;
        int blocks = (n4 + threads - 1) / threads;
        init_kernel<<<blocks, threads>>>(x, out, z0, z1, z2, z3, n4);
    }

    // 2) three scatter-add hops (warp per edge)
    {
        int threads = 256;
        long long total = (long long)E * 32;
        int blocks = (int)((total + threads - 1) / threads);
        edge_kernel<0, 1><<<blocks, threads>>>(x, ei1, w1, out, z0, z1, z2, z3, E);
        edge_kernel<1, 2><<<blocks, threads>>>(x, ei2, w2, out, z0, z1, z2, z3, E);
        edge_kernel<2, 3><<<blocks, threads>>>(x, ei3, w3, out, z0, z1, z2, z3, E);
    }
}